// round 7
// baseline (speedup 1.0000x reference)
#include <cuda_runtime.h>
#include <math.h>

#define N_NODES 25000
#define N_EDGES 400000
#define HID 64
#define HEADS 4
#define D1 (HID*HEADS)

typedef unsigned long long u64;

// ---------------- scratch (static device globals; no allocation) -------------
__device__ float g_h[N_NODES * HID];
__device__ float g_x[N_NODES * D1];
__device__ int   g_deg[N_NODES];
__device__ int   g_off[N_NODES + 1];
__device__ int   g_cur[N_NODES];
__device__ int   g_csr[N_EDGES];

// ---------------- helpers -----------------------------------------------------
__device__ __forceinline__ float ex2_approx(float x) {
    float r;
    asm("ex2.approx.ftz.f32 %0, %1;" : "=f"(r) : "f"(x));
    return r;
}
__device__ __forceinline__ u64 pk2(float lo, float hi) {
    u64 r; asm("mov.b64 %0, {%1, %2};" : "=l"(r) : "f"(lo), "f"(hi)); return r;
}
__device__ __forceinline__ void upk2(float& lo, float& hi, u64 v) {
    asm("mov.b64 {%0, %1}, %2;" : "=f"(lo), "=f"(hi) : "l"(v));
}
__device__ __forceinline__ u64 fma2(u64 a, u64 b, u64 c) {
    u64 r; asm("fma.rn.f32x2 %0, %1, %2, %3;" : "=l"(r) : "l"(a), "l"(b), "l"(c)); return r;
}
__device__ __forceinline__ u64 mul2(u64 a, u64 b) {
    u64 r; asm("mul.rn.f32x2 %0, %1, %2;" : "=l"(r) : "l"(a), "l"(b)); return r;
}
__device__ __forceinline__ u64 add2(u64 a, u64 b) {
    u64 r; asm("add.rn.f32x2 %0, %1, %2;" : "=l"(r) : "l"(a), "l"(b)); return r;
}

// ---------------- CSR build --------------------------------------------------
__global__ void k_count(const int* __restrict__ recv, int* __restrict__ deg, int E) {
    int i = blockIdx.x * blockDim.x + threadIdx.x;
    if (i < E) atomicAdd(&deg[recv[i]], 1);
}

__global__ __launch_bounds__(1024)
void k_scan(const int* __restrict__ deg, int* __restrict__ off,
            int* __restrict__ cur, int n) {
    __shared__ int wsum[32];
    __shared__ int carry_s;
    int t    = threadIdx.x;
    int lane = t & 31;
    int wid  = t >> 5;
    if (t == 0) { carry_s = 0; off[0] = 0; }
    __syncthreads();
    for (int base = 0; base < n; base += 1024) {
        int i = base + t;
        int v = (i < n) ? deg[i] : 0;
        int s = v;
#pragma unroll
        for (int o = 1; o < 32; o <<= 1) {
            int u = __shfl_up_sync(0xffffffffu, s, o);
            if (lane >= o) s += u;
        }
        if (lane == 31) wsum[wid] = s;
        __syncthreads();
        if (wid == 0) {
            int ws = wsum[lane];
#pragma unroll
            for (int o = 1; o < 32; o <<= 1) {
                int u = __shfl_up_sync(0xffffffffu, ws, o);
                if (lane >= o) ws += u;
            }
            wsum[lane] = ws;
        }
        __syncthreads();
        int prev  = (wid > 0) ? wsum[wid - 1] : 0;
        int carry = carry_s;
        int incl  = carry + prev + s;
        if (i < n) {
            off[i + 1] = incl;
            cur[i]     = incl - v;
        }
        __syncthreads();
        if (t == 1023) carry_s = incl;
        __syncthreads();
    }
}

__global__ void k_scatter(const int* __restrict__ recv, const int* __restrict__ send,
                          int* __restrict__ cur, int* __restrict__ csr,
                          int* __restrict__ deg, int E) {
    int i = blockIdx.x * blockDim.x + threadIdx.x;
    if (i < N_NODES) deg[i] = 0;
    if (i < E) {
        int r = recv[i];
        int p = atomicAdd(&cur[r], 1);
        csr[p] = send[i];
    }
}

// ---------------- GEMM v4: R5 structure + register double-buffering ----------
// 64x64 tile, 256 threads, 4x4 microtile, A staged transposed (broadcast
// LDS.128 in inner loop). Global loads for tile k+1 prefetched into registers
// during tile-k compute, hiding L2 latency.
#define GKC 32
#define GAP 68

__global__ __launch_bounds__(256, 4)
void k_gemm(const float* __restrict__ x, const float* __restrict__ Wq,
            const float* __restrict__ bq, float* __restrict__ h,
            int M, int K) {
    __shared__ float As[GKC * GAP];   // As[k*GAP + m] (transposed)
    __shared__ float Bs[GKC * 64];
    int t  = threadIdx.x;
    int tx = t & 15;
    int ty = t >> 4;
    int m0 = blockIdx.x * 64;

    // per-thread staging coordinates
    int rA[2], cA[2], kB[2], cB[2];
#pragma unroll
    for (int i = 0; i < 2; i++) {
        int f = t + i * 256;
        rA[i] = f >> 3;          // A row 0..63
        cA[i] = (f & 7) * 4;     // A k-offset 0..28
        kB[i] = f >> 4;          // B k 0..31
        cB[i] = (f & 15) * 4;    // B col 0..60
    }

    float acc[4][4];
#pragma unroll
    for (int r = 0; r < 4; r++)
#pragma unroll
        for (int c = 0; c < 4; c++) acc[r][c] = 0.f;

    // prefetch tile 0
    float4 aP[2], bP[2];
#pragma unroll
    for (int i = 0; i < 2; i++) {
        int gr = m0 + rA[i];
        aP[i] = (gr < M) ? *(const float4*)&x[gr * K + cA[i]]
                         : make_float4(0.f, 0.f, 0.f, 0.f);
        bP[i] = *(const float4*)&Wq[kB[i] * 64 + cB[i]];
    }

    for (int k0 = 0; k0 < K; k0 += GKC) {
        // store prefetched tile to smem
#pragma unroll
        for (int i = 0; i < 2; i++) {
            As[(cA[i] + 0) * GAP + rA[i]] = aP[i].x;
            As[(cA[i] + 1) * GAP + rA[i]] = aP[i].y;
            As[(cA[i] + 2) * GAP + rA[i]] = aP[i].z;
            As[(cA[i] + 3) * GAP + rA[i]] = aP[i].w;
            *(float4*)&Bs[kB[i] * 64 + cB[i]] = bP[i];
        }
        __syncthreads();
        // prefetch next tile while computing this one
        int k1 = k0 + GKC;
        if (k1 < K) {
#pragma unroll
            for (int i = 0; i < 2; i++) {
                int gr = m0 + rA[i];
                aP[i] = (gr < M) ? *(const float4*)&x[gr * K + k1 + cA[i]]
                                 : make_float4(0.f, 0.f, 0.f, 0.f);
                bP[i] = *(const float4*)&Wq[(k1 + kB[i]) * 64 + cB[i]];
            }
        }
#pragma unroll
        for (int kk = 0; kk < GKC; kk++) {
            float4 av = *(const float4*)&As[kk * GAP + ty * 4];
            float4 bv = *(const float4*)&Bs[kk * 64 + tx * 4];
            float a[4] = {av.x, av.y, av.z, av.w};
            float b[4] = {bv.x, bv.y, bv.z, bv.w};
#pragma unroll
            for (int r = 0; r < 4; r++)
#pragma unroll
                for (int c = 0; c < 4; c++)
                    acc[r][c] = fmaf(a[r], b[c], acc[r][c]);
        }
        __syncthreads();
    }

    float4 bias = *(const float4*)&bq[tx * 4];
#pragma unroll
    for (int r = 0; r < 4; r++) {
        int gr = m0 + ty * 4 + r;
        if (gr < M) {
            float4 o;
            o.x = acc[r][0] + bias.x;
            o.y = acc[r][1] + bias.y;
            o.z = acc[r][2] + bias.z;
            o.w = acc[r][3] + bias.w;
            *(float4*)&h[gr * HID + tx * 4] = o;
        }
    }
}

// ---------------- fused edge attention + aggregate (f32x2 packed) ------------
// One warp per receiver node; lane owns hidden dims (2*lane, 2*lane+1).
// Gather loop unrolled x4 for memory-level parallelism over L2 gathers.
__global__ __launch_bounds__(256)
void k_edge(const float* __restrict__ h, const int* __restrict__ off,
            const int* __restrict__ csr, const float* __restrict__ Wl,
            const float* __restrict__ bl, float* __restrict__ out,
            int n, int last) {
    int w = (blockIdx.x * blockDim.x + threadIdx.x) >> 5;
    if (w >= n) return;
    int lane = threadIdx.x & 31;
    const u64* hv = (const u64*)h;

    float rvx, rvy;
    upk2(rvx, rvy, hv[w * 32 + lane]);

    const float L2E = 1.4426950408889634f;
    const u64 P02 = pk2(0.2f, 0.2f);
    u64 W0p[4], cp[4];
#pragma unroll
    for (int a = 0; a < 4; a++) {
        float w0 = Wl[a] * L2E;
        float w1 = Wl[4 + a];
        float b  = bl[a];
        W0p[a] = pk2(w0, w0);
        cp[a]  = pk2(fmaf(w1, rvx, b) * L2E, fmaf(w1, rvy, b) * L2E);
    }

    int beg = off[w], end = off[w + 1];
    bool has = end > beg;

    u64 den[4], num[4];
#pragma unroll
    for (int a = 0; a < 4; a++) { den[a] = pk2(0.f, 0.f); num[a] = pk2(0.f, 0.f); }

    int i = beg;
    for (; i + 4 <= end; i += 4) {
        int s0 = __ldg(&csr[i]);
        int s1 = __ldg(&csr[i + 1]);
        int s2 = __ldg(&csr[i + 2]);
        int s3 = __ldg(&csr[i + 3]);
        u64 pv[4];
        pv[0] = hv[s0 * 32 + lane];
        pv[1] = hv[s1 * 32 + lane];
        pv[2] = hv[s2 * 32 + lane];
        pv[3] = hv[s3 * 32 + lane];
#pragma unroll
        for (int e = 0; e < 4; e++) {
#pragma unroll
            for (int a = 0; a < 4; a++) {
                u64 z2 = fma2(W0p[a], pv[e], cp[a]);
                u64 zs = mul2(z2, P02);
                float zl, zh, sl, sh;
                upk2(zl, zh, z2); upk2(sl, sh, zs);
                float p0 = ex2_approx(fmaxf(zl, sl));
                float p1 = ex2_approx(fmaxf(zh, sh));
                u64 pp = pk2(p0, p1);
                den[a] = add2(den[a], pp);
                num[a] = fma2(pv[e], pp, num[a]);
            }
        }
    }
    for (; i < end; i++) {
        int sa = __ldg(&csr[i]);
        u64 pva = hv[sa * 32 + lane];
#pragma unroll
        for (int a = 0; a < 4; a++) {
            u64 z2 = fma2(W0p[a], pva, cp[a]);
            u64 zs = mul2(z2, P02);
            float zl, zh, sl, sh;
            upk2(zl, zh, z2); upk2(sl, sh, zs);
            float p0 = ex2_approx(fmaxf(zl, sl));
            float p1 = ex2_approx(fmaxf(zh, sh));
            u64 pp = pk2(p0, p1);
            den[a] = add2(den[a], pp);
            num[a] = fma2(pva, pp, num[a]);
        }
    }

    if (last) {
        float acc0 = 0.f, acc1 = 0.f;
#pragma unroll
        for (int a = 0; a < 4; a++) {
            float n0, n1, d0, d1;
            upk2(n0, n1, num[a]); upk2(d0, d1, den[a]);
            acc0 += has ? __fdividef(n0, d0) : 0.f;
            acc1 += has ? __fdividef(n1, d1) : 0.f;
        }
        float v0 = 0.25f * acc0;
        float v1 = 0.25f * acc1;
        v0 = (v0 > 0.f) ? v0 : expm1f(v0);
        v1 = (v1 > 0.f) ? v1 : expm1f(v1);
        *(float2*)&out[w * HID + 2 * lane] = make_float2(v0, v1);
    } else {
        float o[8];
#pragma unroll
        for (int a = 0; a < 4; a++) {
            float n0, n1, d0, d1;
            upk2(n0, n1, num[a]); upk2(d0, d1, den[a]);
            float g0 = has ? __fdividef(n0, d0) : 0.f;
            float g1 = has ? __fdividef(n1, d1) : 0.f;
            o[a]     = (g0 > 0.f) ? g0 : expm1f(g0);
            o[4 + a] = (g1 > 0.f) ? g1 : expm1f(g1);
        }
        *(float4*)&out[w * D1 + 8 * lane]     = make_float4(o[0], o[1], o[2], o[3]);
        *(float4*)&out[w * D1 + 8 * lane + 4] = make_float4(o[4], o[5], o[6], o[7]);
    }
}

// ---------------- launch ------------------------------------------------------
extern "C" void kernel_launch(void* const* d_in, const int* in_sizes, int n_in,
                              void* d_out, int out_size) {
    const float* nodes = (const float*)d_in[0];
    const int*   send  = (const int*)d_in[1];
    const int*   recv  = (const int*)d_in[2];
    const float* Wq0 = (const float*)d_in[3];
    const float* bq0 = (const float*)d_in[4];
    const float* Wl0 = (const float*)d_in[5];
    const float* bl0 = (const float*)d_in[6];
    const float* Wq1 = (const float*)d_in[7];
    const float* bq1 = (const float*)d_in[8];
    const float* Wl1 = (const float*)d_in[9];
    const float* bl1 = (const float*)d_in[10];
    const float* Wq2 = (const float*)d_in[11];
    const float* bq2 = (const float*)d_in[12];
    const float* Wl2 = (const float*)d_in[13];
    const float* bl2 = (const float*)d_in[14];
    float* out = (float*)d_out;

    float *h, *x;
    int *deg, *off, *cur, *csr;
    cudaGetSymbolAddress((void**)&h,   g_h);
    cudaGetSymbolAddress((void**)&x,   g_x);
    cudaGetSymbolAddress((void**)&deg, g_deg);
    cudaGetSymbolAddress((void**)&off, g_off);
    cudaGetSymbolAddress((void**)&cur, g_cur);
    cudaGetSymbolAddress((void**)&csr, g_csr);

    int gemm_blocks = (N_NODES + 63) / 64;
    int edge_blocks = (N_NODES * 32 + 255) / 256;

    // launch index 3 (k_gemm layer0) is the one ncu profiles — keep it there.
    k_count<<<(N_EDGES + 255) / 256, 256>>>(recv, deg, N_EDGES);          // 0
    k_scan<<<1, 1024>>>(deg, off, cur, N_NODES);                          // 1
    k_scatter<<<(N_EDGES + 255) / 256, 256>>>(recv, send, cur, csr, deg, N_EDGES); // 2
    k_gemm<<<gemm_blocks, 256>>>(nodes, Wq0, bq0, h, N_NODES, 128);       // 3 (profiled)
    k_edge<<<edge_blocks, 256>>>(h, off, csr, Wl0, bl0, x, N_NODES, 0);   // 4
    k_gemm<<<gemm_blocks, 256>>>(x, Wq1, bq1, h, N_NODES, D1);            // 5
    k_edge<<<edge_blocks, 256>>>(h, off, csr, Wl1, bl1, x, N_NODES, 0);   // 6
    k_gemm<<<gemm_blocks, 256>>>(x, Wq2, bq2, h, N_NODES, D1);            // 7
    k_edge<<<edge_blocks, 256>>>(h, off, csr, Wl2, bl2, out, N_NODES, 1); // 8
}

// round 8
// speedup vs baseline: 1.4882x; 1.4882x over previous
#include <cuda_runtime.h>
#include <math.h>

#define N_NODES 25000
#define N_EDGES 400000
#define HID 64
#define HEADS 4
#define D1 (HID*HEADS)

typedef unsigned long long u64;

// ---------------- scratch (static device globals; no allocation) -------------
__device__ float g_h[N_NODES * HID];
__device__ float g_x[N_NODES * D1];
__device__ int   g_deg[N_NODES];
__device__ int   g_off[N_NODES + 1];
__device__ int   g_cur[N_NODES];
__device__ int   g_csr[N_EDGES];

// ---------------- helpers -----------------------------------------------------
__device__ __forceinline__ float ex2_approx(float x) {
    float r;
    asm("ex2.approx.ftz.f32 %0, %1;" : "=f"(r) : "f"(x));
    return r;
}
__device__ __forceinline__ u64 pk2(float lo, float hi) {
    u64 r; asm("mov.b64 %0, {%1, %2};" : "=l"(r) : "f"(lo), "f"(hi)); return r;
}
__device__ __forceinline__ void upk2(float& lo, float& hi, u64 v) {
    asm("mov.b64 {%0, %1}, %2;" : "=f"(lo), "=f"(hi) : "l"(v));
}
__device__ __forceinline__ u64 fma2(u64 a, u64 b, u64 c) {
    u64 r; asm("fma.rn.f32x2 %0, %1, %2, %3;" : "=l"(r) : "l"(a), "l"(b), "l"(c)); return r;
}
__device__ __forceinline__ u64 mul2(u64 a, u64 b) {
    u64 r; asm("mul.rn.f32x2 %0, %1, %2;" : "=l"(r) : "l"(a), "l"(b)); return r;
}
__device__ __forceinline__ u64 add2(u64 a, u64 b) {
    u64 r; asm("add.rn.f32x2 %0, %1, %2;" : "=l"(r) : "l"(a), "l"(b)); return r;
}

// ---------------- CSR build --------------------------------------------------
__global__ void k_count(const int* __restrict__ recv, int* __restrict__ deg, int E) {
    int i = blockIdx.x * blockDim.x + threadIdx.x;
    if (i < E) atomicAdd(&deg[recv[i]], 1);
}

__global__ __launch_bounds__(1024)
void k_scan(const int* __restrict__ deg, int* __restrict__ off,
            int* __restrict__ cur, int n) {
    __shared__ int wsum[32];
    __shared__ int carry_s;
    int t    = threadIdx.x;
    int lane = t & 31;
    int wid  = t >> 5;
    if (t == 0) { carry_s = 0; off[0] = 0; }
    __syncthreads();
    for (int base = 0; base < n; base += 1024) {
        int i = base + t;
        int v = (i < n) ? deg[i] : 0;
        int s = v;
#pragma unroll
        for (int o = 1; o < 32; o <<= 1) {
            int u = __shfl_up_sync(0xffffffffu, s, o);
            if (lane >= o) s += u;
        }
        if (lane == 31) wsum[wid] = s;
        __syncthreads();
        if (wid == 0) {
            int ws = wsum[lane];
#pragma unroll
            for (int o = 1; o < 32; o <<= 1) {
                int u = __shfl_up_sync(0xffffffffu, ws, o);
                if (lane >= o) ws += u;
            }
            wsum[lane] = ws;
        }
        __syncthreads();
        int prev  = (wid > 0) ? wsum[wid - 1] : 0;
        int carry = carry_s;
        int incl  = carry + prev + s;
        if (i < n) {
            off[i + 1] = incl;
            cur[i]     = incl - v;
        }
        __syncthreads();
        if (t == 1023) carry_s = incl;
        __syncthreads();
    }
}

__global__ void k_scatter(const int* __restrict__ recv, const int* __restrict__ send,
                          int* __restrict__ cur, int* __restrict__ csr,
                          int* __restrict__ deg, int E) {
    int i = blockIdx.x * blockDim.x + threadIdx.x;
    if (i < N_NODES) deg[i] = 0;
    if (i < E) {
        int r = recv[i];
        int p = atomicAdd(&cur[r], 1);
        csr[p] = send[i];
    }
}

// ---------------- GEMM (R5 structure, KC=64): h = x @ Wq + bq ----------------
// 64x64 tile, 256 threads, 4x4 microtile, A staged TRANSPOSED so the inner
// loop is 2x LDS.128 broadcast + 16 FFMA. KC=64: half the stage phases and
// barriers of KC=32; 8 independent float4 LDGs per thread per stage (MLP=8).
#define GKC 64
#define GAP 68   // padded A row stride (floats); 68*4 % 16 == 0

__global__ __launch_bounds__(256, 4)
void k_gemm(const float* __restrict__ x, const float* __restrict__ Wq,
            const float* __restrict__ bq, float* __restrict__ h,
            int M, int K) {
    __shared__ float As[GKC * GAP];   // transposed: As[k*GAP + m]
    __shared__ float Bs[GKC * 64];
    int t  = threadIdx.x;
    int tx = t & 15;    // cols 4*tx..+3
    int ty = t >> 4;    // rows 4*ty..+3
    int m0 = blockIdx.x * 64;

    float acc[4][4];
#pragma unroll
    for (int r = 0; r < 4; r++)
#pragma unroll
        for (int c = 0; c < 4; c++) acc[r][c] = 0.f;

    for (int k0 = 0; k0 < K; k0 += GKC) {
        // stage A (64 rows x 64 k), transposed into As[k][m]
#pragma unroll
        for (int i = 0; i < 4; i++) {
            int f  = t + i * 256;        // 0..1023 float4 slots
            int r  = f >> 4;             // row 0..63
            int c4 = (f & 15) * 4;       // k offset 0..60
            int gr = m0 + r;
            float4 v = (gr < M) ? *(const float4*)&x[gr * K + k0 + c4]
                                : make_float4(0.f, 0.f, 0.f, 0.f);
            As[(c4 + 0) * GAP + r] = v.x;
            As[(c4 + 1) * GAP + r] = v.y;
            As[(c4 + 2) * GAP + r] = v.z;
            As[(c4 + 3) * GAP + r] = v.w;
        }
        // stage B (64 k x 64 cols)
#pragma unroll
        for (int i = 0; i < 4; i++) {
            int f  = t + i * 256;
            int kk = f >> 4;
            int c4 = (f & 15) * 4;
            *(float4*)&Bs[kk * 64 + c4] = *(const float4*)&Wq[(k0 + kk) * 64 + c4];
        }
        __syncthreads();
#pragma unroll 16
        for (int kk = 0; kk < GKC; kk++) {
            float4 av = *(const float4*)&As[kk * GAP + ty * 4];
            float4 bv = *(const float4*)&Bs[kk * 64 + tx * 4];
            float a[4] = {av.x, av.y, av.z, av.w};
            float b[4] = {bv.x, bv.y, bv.z, bv.w};
#pragma unroll
            for (int r = 0; r < 4; r++)
#pragma unroll
                for (int c = 0; c < 4; c++)
                    acc[r][c] = fmaf(a[r], b[c], acc[r][c]);
        }
        __syncthreads();
    }

    float4 bias = *(const float4*)&bq[tx * 4];
#pragma unroll
    for (int r = 0; r < 4; r++) {
        int gr = m0 + ty * 4 + r;
        if (gr < M) {
            float4 o;
            o.x = acc[r][0] + bias.x;
            o.y = acc[r][1] + bias.y;
            o.z = acc[r][2] + bias.z;
            o.w = acc[r][3] + bias.w;
            *(float4*)&h[gr * HID + tx * 4] = o;
        }
    }
}

// ---------------- fused edge attention + aggregate (f32x2 packed, R5) --------
__global__ __launch_bounds__(256)
void k_edge(const float* __restrict__ h, const int* __restrict__ off,
            const int* __restrict__ csr, const float* __restrict__ Wl,
            const float* __restrict__ bl, float* __restrict__ out,
            int n, int last) {
    int w = (blockIdx.x * blockDim.x + threadIdx.x) >> 5;
    if (w >= n) return;
    int lane = threadIdx.x & 31;
    const u64* hv = (const u64*)h;

    float rvx, rvy;
    upk2(rvx, rvy, hv[w * 32 + lane]);

    const float L2E = 1.4426950408889634f;
    const u64 P02 = pk2(0.2f, 0.2f);
    u64 W0p[4], cp[4];
#pragma unroll
    for (int a = 0; a < 4; a++) {
        float w0 = Wl[a] * L2E;
        float w1 = Wl[4 + a];
        float b  = bl[a];
        W0p[a] = pk2(w0, w0);
        cp[a]  = pk2(fmaf(w1, rvx, b) * L2E, fmaf(w1, rvy, b) * L2E);
    }

    int beg = off[w], end = off[w + 1];
    bool has = end > beg;

    u64 den[4], num[4];
#pragma unroll
    for (int a = 0; a < 4; a++) { den[a] = pk2(0.f, 0.f); num[a] = pk2(0.f, 0.f); }

    int i = beg;
    for (; i + 2 <= end; i += 2) {
        int sa = __ldg(&csr[i]);
        int sb = __ldg(&csr[i + 1]);
        u64 pva = hv[sa * 32 + lane];
        u64 pvb = hv[sb * 32 + lane];
#pragma unroll
        for (int a = 0; a < 4; a++) {
            u64 z2 = fma2(W0p[a], pva, cp[a]);
            u64 zs = mul2(z2, P02);
            float zl, zh, sl, sh;
            upk2(zl, zh, z2); upk2(sl, sh, zs);
            float p0 = ex2_approx(fmaxf(zl, sl));
            float p1 = ex2_approx(fmaxf(zh, sh));
            u64 pp = pk2(p0, p1);
            den[a] = add2(den[a], pp);
            num[a] = fma2(pva, pp, num[a]);
        }
#pragma unroll
        for (int a = 0; a < 4; a++) {
            u64 z2 = fma2(W0p[a], pvb, cp[a]);
            u64 zs = mul2(z2, P02);
            float zl, zh, sl, sh;
            upk2(zl, zh, z2); upk2(sl, sh, zs);
            float p0 = ex2_approx(fmaxf(zl, sl));
            float p1 = ex2_approx(fmaxf(zh, sh));
            u64 pp = pk2(p0, p1);
            den[a] = add2(den[a], pp);
            num[a] = fma2(pvb, pp, num[a]);
        }
    }
    if (i < end) {
        int sa = __ldg(&csr[i]);
        u64 pva = hv[sa * 32 + lane];
#pragma unroll
        for (int a = 0; a < 4; a++) {
            u64 z2 = fma2(W0p[a], pva, cp[a]);
            u64 zs = mul2(z2, P02);
            float zl, zh, sl, sh;
            upk2(zl, zh, z2); upk2(sl, sh, zs);
            float p0 = ex2_approx(fmaxf(zl, sl));
            float p1 = ex2_approx(fmaxf(zh, sh));
            u64 pp = pk2(p0, p1);
            den[a] = add2(den[a], pp);
            num[a] = fma2(pva, pp, num[a]);
        }
    }

    if (last) {
        float acc0 = 0.f, acc1 = 0.f;
#pragma unroll
        for (int a = 0; a < 4; a++) {
            float n0, n1, d0, d1;
            upk2(n0, n1, num[a]); upk2(d0, d1, den[a]);
            acc0 += has ? __fdividef(n0, d0) : 0.f;
            acc1 += has ? __fdividef(n1, d1) : 0.f;
        }
        float v0 = 0.25f * acc0;
        float v1 = 0.25f * acc1;
        v0 = (v0 > 0.f) ? v0 : expm1f(v0);
        v1 = (v1 > 0.f) ? v1 : expm1f(v1);
        *(float2*)&out[w * HID + 2 * lane] = make_float2(v0, v1);
    } else {
        float o[8];
#pragma unroll
        for (int a = 0; a < 4; a++) {
            float n0, n1, d0, d1;
            upk2(n0, n1, num[a]); upk2(d0, d1, den[a]);
            float g0 = has ? __fdividef(n0, d0) : 0.f;
            float g1 = has ? __fdividef(n1, d1) : 0.f;
            o[a]     = (g0 > 0.f) ? g0 : expm1f(g0);
            o[4 + a] = (g1 > 0.f) ? g1 : expm1f(g1);
        }
        *(float4*)&out[w * D1 + 8 * lane]     = make_float4(o[0], o[1], o[2], o[3]);
        *(float4*)&out[w * D1 + 8 * lane + 4] = make_float4(o[4], o[5], o[6], o[7]);
    }
}

// ---------------- launch ------------------------------------------------------
extern "C" void kernel_launch(void* const* d_in, const int* in_sizes, int n_in,
                              void* d_out, int out_size) {
    const float* nodes = (const float*)d_in[0];
    const int*   send  = (const int*)d_in[1];
    const int*   recv  = (const int*)d_in[2];
    const float* Wq0 = (const float*)d_in[3];
    const float* bq0 = (const float*)d_in[4];
    const float* Wl0 = (const float*)d_in[5];
    const float* bl0 = (const float*)d_in[6];
    const float* Wq1 = (const float*)d_in[7];
    const float* bq1 = (const float*)d_in[8];
    const float* Wl1 = (const float*)d_in[9];
    const float* bl1 = (const float*)d_in[10];
    const float* Wq2 = (const float*)d_in[11];
    const float* bq2 = (const float*)d_in[12];
    const float* Wl2 = (const float*)d_in[13];
    const float* bl2 = (const float*)d_in[14];
    float* out = (float*)d_out;

    float *h, *x;
    int *deg, *off, *cur, *csr;
    cudaGetSymbolAddress((void**)&h,   g_h);
    cudaGetSymbolAddress((void**)&x,   g_x);
    cudaGetSymbolAddress((void**)&deg, g_deg);
    cudaGetSymbolAddress((void**)&off, g_off);
    cudaGetSymbolAddress((void**)&cur, g_cur);
    cudaGetSymbolAddress((void**)&csr, g_csr);

    int gemm_blocks = (N_NODES + 63) / 64;
    int edge_blocks = (N_NODES * 32 + 255) / 256;

    // launch index 3 (k_gemm layer0) is the one ncu profiles — keep it there.
    k_count<<<(N_EDGES + 255) / 256, 256>>>(recv, deg, N_EDGES);          // 0
    k_scan<<<1, 1024>>>(deg, off, cur, N_NODES);                          // 1
    k_scatter<<<(N_EDGES + 255) / 256, 256>>>(recv, send, cur, csr, deg, N_EDGES); // 2
    k_gemm<<<gemm_blocks, 256>>>(nodes, Wq0, bq0, h, N_NODES, 128);       // 3 (profiled)
    k_edge<<<edge_blocks, 256>>>(h, off, csr, Wl0, bl0, x, N_NODES, 0);   // 4
    k_gemm<<<gemm_blocks, 256>>>(x, Wq1, bq1, h, N_NODES, D1);            // 5
    k_edge<<<edge_blocks, 256>>>(h, off, csr, Wl1, bl1, x, N_NODES, 0);   // 6
    k_gemm<<<gemm_blocks, 256>>>(x, Wq2, bq2, h, N_NODES, D1);            // 7
    k_edge<<<edge_blocks, 256>>>(h, off, csr, Wl2, bl2, out, N_NODES, 1); // 8
}

// round 11
// speedup vs baseline: 1.5962x; 1.0726x over previous
#include <cuda_runtime.h>
#include <math.h>

#define N_NODES 25000
#define N_EDGES 400000
#define HID 64
#define HEADS 4
#define D1 (HID*HEADS)

typedef unsigned long long u64;
typedef unsigned int u32;

// ---------------- scratch (static device globals; no allocation) -------------
__device__ float g_h[N_NODES * HID];
__device__ float g_x[N_NODES * D1];
__device__ int   g_deg[N_NODES];
__device__ int   g_off[N_NODES + 1];
__device__ int   g_cur[N_NODES];
__device__ int   g_csr[N_EDGES];

// ---------------- helpers -----------------------------------------------------
__device__ __forceinline__ float ex2_approx(float x) {
    float r;
    asm("ex2.approx.ftz.f32 %0, %1;" : "=f"(r) : "f"(x));
    return r;
}
__device__ __forceinline__ u64 pk2(float lo, float hi) {
    u64 r; asm("mov.b64 %0, {%1, %2};" : "=l"(r) : "f"(lo), "f"(hi)); return r;
}
__device__ __forceinline__ void upk2(float& lo, float& hi, u64 v) {
    asm("mov.b64 {%0, %1}, %2;" : "=f"(lo), "=f"(hi) : "l"(v));
}
__device__ __forceinline__ u64 fma2(u64 a, u64 b, u64 c) {
    u64 r; asm("fma.rn.f32x2 %0, %1, %2, %3;" : "=l"(r) : "l"(a), "l"(b), "l"(c)); return r;
}
__device__ __forceinline__ u64 mul2(u64 a, u64 b) {
    u64 r; asm("mul.rn.f32x2 %0, %1, %2;" : "=l"(r) : "l"(a), "l"(b)); return r;
}
__device__ __forceinline__ u64 add2(u64 a, u64 b) {
    u64 r; asm("add.rn.f32x2 %0, %1, %2;" : "=l"(r) : "l"(a), "l"(b)); return r;
}
__device__ __forceinline__ u32 s2u(const void* p) {
    u32 a;
    asm("{ .reg .u64 t; cvta.to.shared.u64 t, %1; cvt.u32.u64 %0, t; }" : "=r"(a) : "l"(p));
    return a;
}
__device__ __forceinline__ void cp16(u32 dst, const void* src) {
    asm volatile("cp.async.cg.shared.global [%0], [%1], 16;" :: "r"(dst), "l"(src));
}
__device__ __forceinline__ void cp_commit() {
    asm volatile("cp.async.commit_group;" ::: "memory");
}
template <int N>
__device__ __forceinline__ void cp_wait() {
    asm volatile("cp.async.wait_group %0;" :: "n"(N) : "memory");
}

// ---------------- CSR build --------------------------------------------------
__global__ void k_count(const int* __restrict__ recv, int* __restrict__ deg, int E) {
    int i = blockIdx.x * blockDim.x + threadIdx.x;
    if (i < E) atomicAdd(&deg[recv[i]], 1);
}

__global__ __launch_bounds__(1024)
void k_scan(const int* __restrict__ deg, int* __restrict__ off,
            int* __restrict__ cur, int n) {
    __shared__ int wsum[32];
    __shared__ int carry_s;
    int t    = threadIdx.x;
    int lane = t & 31;
    int wid  = t >> 5;
    if (t == 0) { carry_s = 0; off[0] = 0; }
    __syncthreads();
    for (int base = 0; base < n; base += 1024) {
        int i = base + t;
        int v = (i < n) ? deg[i] : 0;
        int s = v;
#pragma unroll
        for (int o = 1; o < 32; o <<= 1) {
            int u = __shfl_up_sync(0xffffffffu, s, o);
            if (lane >= o) s += u;
        }
        if (lane == 31) wsum[wid] = s;
        __syncthreads();
        if (wid == 0) {
            int ws = wsum[lane];
#pragma unroll
            for (int o = 1; o < 32; o <<= 1) {
                int u = __shfl_up_sync(0xffffffffu, ws, o);
                if (lane >= o) ws += u;
            }
            wsum[lane] = ws;
        }
        __syncthreads();
        int prev  = (wid > 0) ? wsum[wid - 1] : 0;
        int carry = carry_s;
        int incl  = carry + prev + s;
        if (i < n) {
            off[i + 1] = incl;
            cur[i]     = incl - v;
        }
        __syncthreads();
        if (t == 1023) carry_s = incl;
        __syncthreads();
    }
}

__global__ void k_scatter(const int* __restrict__ recv, const int* __restrict__ send,
                          int* __restrict__ cur, int* __restrict__ csr,
                          int* __restrict__ deg, int E) {
    int i = blockIdx.x * blockDim.x + threadIdx.x;
    if (i < N_NODES) deg[i] = 0;
    if (i < E) {
        int r = recv[i];
        int p = atomicAdd(&cur[r], 1);
        csr[p] = send[i];
    }
}

// ---------------- GEMM v5: cp.async double-buffered --------------------------
// 64x64 tile, 256 threads, 4x4 microtile. A row-major smem (stride 36 floats,
// 16B-aligned rows), B row-major. Inner loop in k-groups of 4:
// 8x LDS.128 + 64 FFMA per thread. cp.async prefetches tile k+1 into the
// other buffer while tile k computes -> L2 latency off the critical path.
#define GKC 32
#define AST 36   // A row stride in floats (144 B, 16B-aligned)

__global__ __launch_bounds__(256, 4)
void k_gemm(const float* __restrict__ x, const float* __restrict__ Wq,
            const float* __restrict__ bq, float* __restrict__ h,
            int M, int K) {
    __shared__ float As[2][64 * AST];
    __shared__ float Bs[2][GKC * 64];
    int t  = threadIdx.x;
    int tx = t & 15;    // cols 4*tx..+3
    int ty = t >> 4;    // rows 4*ty..+3
    int m0 = blockIdx.x * 64;

    // staging coordinates (2 A-chunks + 2 B-chunks of 16B per thread)
    int rA[2], cA[2], kB[2], cB[2];
#pragma unroll
    for (int i = 0; i < 2; i++) {
        int f = t + i * 256;
        rA[i] = f >> 3;          // A row 0..63
        cA[i] = (f & 7) * 4;     // A k-offset 0..28
        kB[i] = f >> 4;          // B k 0..31
        cB[i] = (f & 15) * 4;    // B col 0..60
    }
    u32 aBase[2], bBase[2];
#pragma unroll
    for (int b = 0; b < 2; b++) {
        aBase[b] = s2u(&As[b][0]);
        bBase[b] = s2u(&Bs[b][0]);
    }

    float acc[4][4];
#pragma unroll
    for (int r = 0; r < 4; r++)
#pragma unroll
        for (int c = 0; c < 4; c++) acc[r][c] = 0.f;

    int ntiles = K / GKC;

    // stage tile 0 into buffer 0
#pragma unroll
    for (int i = 0; i < 2; i++) {
        int gr = m0 + rA[i];
        u32 da = aBase[0] + (u32)(rA[i] * AST + cA[i]) * 4u;
        if (gr < M) cp16(da, &x[gr * K + cA[i]]);
        else        *(float4*)&As[0][rA[i] * AST + cA[i]] = make_float4(0.f, 0.f, 0.f, 0.f);
        u32 db = bBase[0] + (u32)(kB[i] * 64 + cB[i]) * 4u;
        cp16(db, &Wq[kB[i] * 64 + cB[i]]);
    }
    cp_commit();

    for (int c = 0; c < ntiles; c++) {
        int buf = c & 1;
        if (c + 1 < ntiles) {
            int k1 = (c + 1) * GKC;
            int nb = buf ^ 1;
#pragma unroll
            for (int i = 0; i < 2; i++) {
                int gr = m0 + rA[i];
                u32 da = aBase[nb] + (u32)(rA[i] * AST + cA[i]) * 4u;
                if (gr < M) cp16(da, &x[gr * K + k1 + cA[i]]);
                else        *(float4*)&As[nb][rA[i] * AST + cA[i]] = make_float4(0.f, 0.f, 0.f, 0.f);
                u32 db = bBase[nb] + (u32)(kB[i] * 64 + cB[i]) * 4u;
                cp16(db, &Wq[(k1 + kB[i]) * 64 + cB[i]]);
            }
            cp_commit();
            cp_wait<1>();   // current tile's group complete; next may be in flight
        } else {
            cp_wait<0>();
        }
        __syncthreads();

#pragma unroll
        for (int k4 = 0; k4 < GKC; k4 += 4) {
            float4 a4[4], b4[4];
#pragma unroll
            for (int r = 0; r < 4; r++)
                a4[r] = *(const float4*)&As[buf][(ty * 4 + r) * AST + k4];
#pragma unroll
            for (int k = 0; k < 4; k++)
                b4[k] = *(const float4*)&Bs[buf][(k4 + k) * 64 + tx * 4];
#pragma unroll
            for (int r = 0; r < 4; r++) {
                acc[r][0] = fmaf(a4[r].x, b4[0].x, acc[r][0]);
                acc[r][1] = fmaf(a4[r].x, b4[0].y, acc[r][1]);
                acc[r][2] = fmaf(a4[r].x, b4[0].z, acc[r][2]);
                acc[r][3] = fmaf(a4[r].x, b4[0].w, acc[r][3]);
                acc[r][0] = fmaf(a4[r].y, b4[1].x, acc[r][0]);
                acc[r][1] = fmaf(a4[r].y, b4[1].y, acc[r][1]);
                acc[r][2] = fmaf(a4[r].y, b4[1].z, acc[r][2]);
                acc[r][3] = fmaf(a4[r].y, b4[1].w, acc[r][3]);
                acc[r][0] = fmaf(a4[r].z, b4[2].x, acc[r][0]);
                acc[r][1] = fmaf(a4[r].z, b4[2].y, acc[r][1]);
                acc[r][2] = fmaf(a4[r].z, b4[2].z, acc[r][2]);
                acc[r][3] = fmaf(a4[r].z, b4[2].w, acc[r][3]);
                acc[r][0] = fmaf(a4[r].w, b4[3].x, acc[r][0]);
                acc[r][1] = fmaf(a4[r].w, b4[3].y, acc[r][1]);
                acc[r][2] = fmaf(a4[r].w, b4[3].z, acc[r][2]);
                acc[r][3] = fmaf(a4[r].w, b4[3].w, acc[r][3]);
            }
        }
        __syncthreads();
    }

    float4 bias = *(const float4*)&bq[tx * 4];
#pragma unroll
    for (int r = 0; r < 4; r++) {
        int gr = m0 + ty * 4 + r;
        if (gr < M) {
            float4 o;
            o.x = acc[r][0] + bias.x;
            o.y = acc[r][1] + bias.y;
            o.z = acc[r][2] + bias.z;
            o.w = acc[r][3] + bias.w;
            *(float4*)&h[gr * HID + tx * 4] = o;
        }
    }
}

// ---------------- fused edge attention + aggregate (f32x2 packed, R5) --------
__global__ __launch_bounds__(256)
void k_edge(const float* __restrict__ h, const int* __restrict__ off,
            const int* __restrict__ csr, const float* __restrict__ Wl,
            const float* __restrict__ bl, float* __restrict__ out,
            int n, int last) {
    int w = (blockIdx.x * blockDim.x + threadIdx.x) >> 5;
    if (w >= n) return;
    int lane = threadIdx.x & 31;
    const u64* hv = (const u64*)h;

    float rvx, rvy;
    upk2(rvx, rvy, hv[w * 32 + lane]);

    const float L2E = 1.4426950408889634f;
    const u64 P02 = pk2(0.2f, 0.2f);
    u64 W0p[4], cp[4];
#pragma unroll
    for (int a = 0; a < 4; a++) {
        float w0 = Wl[a] * L2E;
        float w1 = Wl[4 + a];
        float b  = bl[a];
        W0p[a] = pk2(w0, w0);
        cp[a]  = pk2(fmaf(w1, rvx, b) * L2E, fmaf(w1, rvy, b) * L2E);
    }

    int beg = off[w], end = off[w + 1];
    bool has = end > beg;

    u64 den[4], num[4];
#pragma unroll
    for (int a = 0; a < 4; a++) { den[a] = pk2(0.f, 0.f); num[a] = pk2(0.f, 0.f); }

    int i = beg;
    for (; i + 2 <= end; i += 2) {
        int sa = __ldg(&csr[i]);
        int sb = __ldg(&csr[i + 1]);
        u64 pva = hv[sa * 32 + lane];
        u64 pvb = hv[sb * 32 + lane];
#pragma unroll
        for (int a = 0; a < 4; a++) {
            u64 z2 = fma2(W0p[a], pva, cp[a]);
            u64 zs = mul2(z2, P02);
            float zl, zh, sl, sh;
            upk2(zl, zh, z2); upk2(sl, sh, zs);
            float p0 = ex2_approx(fmaxf(zl, sl));
            float p1 = ex2_approx(fmaxf(zh, sh));
            u64 pp = pk2(p0, p1);
            den[a] = add2(den[a], pp);
            num[a] = fma2(pva, pp, num[a]);
        }
#pragma unroll
        for (int a = 0; a < 4; a++) {
            u64 z2 = fma2(W0p[a], pvb, cp[a]);
            u64 zs = mul2(z2, P02);
            float zl, zh, sl, sh;
            upk2(zl, zh, z2); upk2(sl, sh, zs);
            float p0 = ex2_approx(fmaxf(zl, sl));
            float p1 = ex2_approx(fmaxf(zh, sh));
            u64 pp = pk2(p0, p1);
            den[a] = add2(den[a], pp);
            num[a] = fma2(pvb, pp, num[a]);
        }
    }
    if (i < end) {
        int sa = __ldg(&csr[i]);
        u64 pva = hv[sa * 32 + lane];
#pragma unroll
        for (int a = 0; a < 4; a++) {
            u64 z2 = fma2(W0p[a], pva, cp[a]);
            u64 zs = mul2(z2, P02);
            float zl, zh, sl, sh;
            upk2(zl, zh, z2); upk2(sl, sh, zs);
            float p0 = ex2_approx(fmaxf(zl, sl));
            float p1 = ex2_approx(fmaxf(zh, sh));
            u64 pp = pk2(p0, p1);
            den[a] = add2(den[a], pp);
            num[a] = fma2(pva, pp, num[a]);
        }
    }

    if (last) {
        float acc0 = 0.f, acc1 = 0.f;
#pragma unroll
        for (int a = 0; a < 4; a++) {
            float n0, n1, d0, d1;
            upk2(n0, n1, num[a]); upk2(d0, d1, den[a]);
            acc0 += has ? __fdividef(n0, d0) : 0.f;
            acc1 += has ? __fdividef(n1, d1) : 0.f;
        }
        float v0 = 0.25f * acc0;
        float v1 = 0.25f * acc1;
        v0 = (v0 > 0.f) ? v0 : expm1f(v0);
        v1 = (v1 > 0.f) ? v1 : expm1f(v1);
        *(float2*)&out[w * HID + 2 * lane] = make_float2(v0, v1);
    } else {
        float o[8];
#pragma unroll
        for (int a = 0; a < 4; a++) {
            float n0, n1, d0, d1;
            upk2(n0, n1, num[a]); upk2(d0, d1, den[a]);
            float g0 = has ? __fdividef(n0, d0) : 0.f;
            float g1 = has ? __fdividef(n1, d1) : 0.f;
            o[a]     = (g0 > 0.f) ? g0 : expm1f(g0);
            o[4 + a] = (g1 > 0.f) ? g1 : expm1f(g1);
        }
        *(float4*)&out[w * D1 + 8 * lane]     = make_float4(o[0], o[1], o[2], o[3]);
        *(float4*)&out[w * D1 + 8 * lane + 4] = make_float4(o[4], o[5], o[6], o[7]);
    }
}

// ---------------- launch ------------------------------------------------------
extern "C" void kernel_launch(void* const* d_in, const int* in_sizes, int n_in,
                              void* d_out, int out_size) {
    const float* nodes = (const float*)d_in[0];
    const int*   send  = (const int*)d_in[1];
    const int*   recv  = (const int*)d_in[2];
    const float* Wq0 = (const float*)d_in[3];
    const float* bq0 = (const float*)d_in[4];
    const float* Wl0 = (const float*)d_in[5];
    const float* bl0 = (const float*)d_in[6];
    const float* Wq1 = (const float*)d_in[7];
    const float* bq1 = (const float*)d_in[8];
    const float* Wl1 = (const float*)d_in[9];
    const float* bl1 = (const float*)d_in[10];
    const float* Wq2 = (const float*)d_in[11];
    const float* bq2 = (const float*)d_in[12];
    const float* Wl2 = (const float*)d_in[13];
    const float* bl2 = (const float*)d_in[14];
    float* out = (float*)d_out;

    float *h, *x;
    int *deg, *off, *cur, *csr;
    cudaGetSymbolAddress((void**)&h,   g_h);
    cudaGetSymbolAddress((void**)&x,   g_x);
    cudaGetSymbolAddress((void**)&deg, g_deg);
    cudaGetSymbolAddress((void**)&off, g_off);
    cudaGetSymbolAddress((void**)&cur, g_cur);
    cudaGetSymbolAddress((void**)&csr, g_csr);

    int gemm_blocks = (N_NODES + 63) / 64;
    int edge_blocks = (N_NODES * 32 + 255) / 256;

    // launch index 3 (k_gemm layer0) is the one ncu profiles — keep it there.
    k_count<<<(N_EDGES + 255) / 256, 256>>>(recv, deg, N_EDGES);          // 0
    k_scan<<<1, 1024>>>(deg, off, cur, N_NODES);                          // 1
    k_scatter<<<(N_EDGES + 255) / 256, 256>>>(recv, send, cur, csr, deg, N_EDGES); // 2
    k_gemm<<<gemm_blocks, 256>>>(nodes, Wq0, bq0, h, N_NODES, 128);       // 3 (profiled)
    k_edge<<<edge_blocks, 256>>>(h, off, csr, Wl0, bl0, x, N_NODES, 0);   // 4
    k_gemm<<<gemm_blocks, 256>>>(x, Wq1, bq1, h, N_NODES, D1);            // 5
    k_edge<<<edge_blocks, 256>>>(h, off, csr, Wl1, bl1, x, N_NODES, 0);   // 6
    k_gemm<<<gemm_blocks, 256>>>(x, Wq2, bq2, h, N_NODES, D1);            // 7
    k_edge<<<edge_blocks, 256>>>(h, off, csr, Wl2, bl2, out, N_NODES, 1); // 8
}

// round 12
// speedup vs baseline: 1.6804x; 1.0527x over previous
#include <cuda_runtime.h>
#include <math.h>

#define N_NODES 25000
#define N_EDGES 400000
#define HID 64
#define HEADS 4
#define D1 (HID*HEADS)

typedef unsigned long long u64;
typedef unsigned int u32;

// ---------------- scratch (static device globals; no allocation) -------------
__device__ float g_h[N_NODES * HID];
__device__ float g_x[N_NODES * D1];
__device__ int   g_deg[N_NODES];
__device__ int   g_off[N_NODES + 1];
__device__ int   g_cur[N_NODES];
__device__ int   g_csr[N_EDGES];

// ---------------- helpers -----------------------------------------------------
__device__ __forceinline__ float ex2_approx(float x) {
    float r;
    asm("ex2.approx.ftz.f32 %0, %1;" : "=f"(r) : "f"(x));
    return r;
}
__device__ __forceinline__ u64 pk2(float lo, float hi) {
    u64 r; asm("mov.b64 %0, {%1, %2};" : "=l"(r) : "f"(lo), "f"(hi)); return r;
}
__device__ __forceinline__ void upk2(float& lo, float& hi, u64 v) {
    asm("mov.b64 {%0, %1}, %2;" : "=f"(lo), "=f"(hi) : "l"(v));
}
__device__ __forceinline__ u64 fma2(u64 a, u64 b, u64 c) {
    u64 r; asm("fma.rn.f32x2 %0, %1, %2, %3;" : "=l"(r) : "l"(a), "l"(b), "l"(c)); return r;
}
__device__ __forceinline__ u64 mul2(u64 a, u64 b) {
    u64 r; asm("mul.rn.f32x2 %0, %1, %2;" : "=l"(r) : "l"(a), "l"(b)); return r;
}
__device__ __forceinline__ u64 add2(u64 a, u64 b) {
    u64 r; asm("add.rn.f32x2 %0, %1, %2;" : "=l"(r) : "l"(a), "l"(b)); return r;
}
__device__ __forceinline__ u32 s2u(const void* p) {
    u32 a;
    asm("{ .reg .u64 t; cvta.to.shared.u64 t, %1; cvt.u32.u64 %0, t; }" : "=r"(a) : "l"(p));
    return a;
}
__device__ __forceinline__ void cp16(u32 dst, const void* src) {
    asm volatile("cp.async.cg.shared.global [%0], [%1], 16;" :: "r"(dst), "l"(src));
}
__device__ __forceinline__ void cp_commit() {
    asm volatile("cp.async.commit_group;" ::: "memory");
}
template <int N>
__device__ __forceinline__ void cp_wait() {
    asm volatile("cp.async.wait_group %0;" :: "n"(N) : "memory");
}

// ---------------- CSR build --------------------------------------------------
__global__ void k_count(const int* __restrict__ recv, int* __restrict__ deg, int E) {
    int i = blockIdx.x * blockDim.x + threadIdx.x;
    if (i < E) atomicAdd(&deg[recv[i]], 1);
}

__global__ __launch_bounds__(1024)
void k_scan(const int* __restrict__ deg, int* __restrict__ off,
            int* __restrict__ cur, int n) {
    __shared__ int wsum[32];
    __shared__ int carry_s;
    int t    = threadIdx.x;
    int lane = t & 31;
    int wid  = t >> 5;
    if (t == 0) { carry_s = 0; off[0] = 0; }
    __syncthreads();
    for (int base = 0; base < n; base += 1024) {
        int i = base + t;
        int v = (i < n) ? deg[i] : 0;
        int s = v;
#pragma unroll
        for (int o = 1; o < 32; o <<= 1) {
            int u = __shfl_up_sync(0xffffffffu, s, o);
            if (lane >= o) s += u;
        }
        if (lane == 31) wsum[wid] = s;
        __syncthreads();
        if (wid == 0) {
            int ws = wsum[lane];
#pragma unroll
            for (int o = 1; o < 32; o <<= 1) {
                int u = __shfl_up_sync(0xffffffffu, ws, o);
                if (lane >= o) ws += u;
            }
            wsum[lane] = ws;
        }
        __syncthreads();
        int prev  = (wid > 0) ? wsum[wid - 1] : 0;
        int carry = carry_s;
        int incl  = carry + prev + s;
        if (i < n) {
            off[i + 1] = incl;
            cur[i]     = incl - v;
        }
        __syncthreads();
        if (t == 1023) carry_s = incl;
        __syncthreads();
    }
}

__global__ void k_scatter(const int* __restrict__ recv, const int* __restrict__ send,
                          int* __restrict__ cur, int* __restrict__ csr,
                          int* __restrict__ deg, int E) {
    int i = blockIdx.x * blockDim.x + threadIdx.x;
    if (i < N_NODES) deg[i] = 0;
    if (i < E) {
        int r = recv[i];
        int p = atomicAdd(&cur[r], 1);
        csr[p] = send[i];
    }
}

// ---------------- GEMM v5: cp.async double-buffered --------------------------
#define GKC 32
#define AST 36   // A row stride in floats (144 B, 16B-aligned)

__global__ __launch_bounds__(256, 4)
void k_gemm(const float* __restrict__ x, const float* __restrict__ Wq,
            const float* __restrict__ bq, float* __restrict__ h,
            int M, int K) {
    __shared__ float As[2][64 * AST];
    __shared__ float Bs[2][GKC * 64];
    int t  = threadIdx.x;
    int tx = t & 15;
    int ty = t >> 4;
    int m0 = blockIdx.x * 64;

    int rA[2], cA[2], kB[2], cB[2];
#pragma unroll
    for (int i = 0; i < 2; i++) {
        int f = t + i * 256;
        rA[i] = f >> 3;
        cA[i] = (f & 7) * 4;
        kB[i] = f >> 4;
        cB[i] = (f & 15) * 4;
    }
    u32 aBase[2], bBase[2];
#pragma unroll
    for (int b = 0; b < 2; b++) {
        aBase[b] = s2u(&As[b][0]);
        bBase[b] = s2u(&Bs[b][0]);
    }

    float acc[4][4];
#pragma unroll
    for (int r = 0; r < 4; r++)
#pragma unroll
        for (int c = 0; c < 4; c++) acc[r][c] = 0.f;

    int ntiles = K / GKC;

#pragma unroll
    for (int i = 0; i < 2; i++) {
        int gr = m0 + rA[i];
        u32 da = aBase[0] + (u32)(rA[i] * AST + cA[i]) * 4u;
        if (gr < M) cp16(da, &x[gr * K + cA[i]]);
        else        *(float4*)&As[0][rA[i] * AST + cA[i]] = make_float4(0.f, 0.f, 0.f, 0.f);
        u32 db = bBase[0] + (u32)(kB[i] * 64 + cB[i]) * 4u;
        cp16(db, &Wq[kB[i] * 64 + cB[i]]);
    }
    cp_commit();

    for (int c = 0; c < ntiles; c++) {
        int buf = c & 1;
        if (c + 1 < ntiles) {
            int k1 = (c + 1) * GKC;
            int nb = buf ^ 1;
#pragma unroll
            for (int i = 0; i < 2; i++) {
                int gr = m0 + rA[i];
                u32 da = aBase[nb] + (u32)(rA[i] * AST + cA[i]) * 4u;
                if (gr < M) cp16(da, &x[gr * K + k1 + cA[i]]);
                else        *(float4*)&As[nb][rA[i] * AST + cA[i]] = make_float4(0.f, 0.f, 0.f, 0.f);
                u32 db = bBase[nb] + (u32)(kB[i] * 64 + cB[i]) * 4u;
                cp16(db, &Wq[(k1 + kB[i]) * 64 + cB[i]]);
            }
            cp_commit();
            cp_wait<1>();
        } else {
            cp_wait<0>();
        }
        __syncthreads();

#pragma unroll
        for (int k4 = 0; k4 < GKC; k4 += 4) {
            float4 a4[4], b4[4];
#pragma unroll
            for (int r = 0; r < 4; r++)
                a4[r] = *(const float4*)&As[buf][(ty * 4 + r) * AST + k4];
#pragma unroll
            for (int k = 0; k < 4; k++)
                b4[k] = *(const float4*)&Bs[buf][(k4 + k) * 64 + tx * 4];
#pragma unroll
            for (int r = 0; r < 4; r++) {
                acc[r][0] = fmaf(a4[r].x, b4[0].x, acc[r][0]);
                acc[r][1] = fmaf(a4[r].x, b4[0].y, acc[r][1]);
                acc[r][2] = fmaf(a4[r].x, b4[0].z, acc[r][2]);
                acc[r][3] = fmaf(a4[r].x, b4[0].w, acc[r][3]);
                acc[r][0] = fmaf(a4[r].y, b4[1].x, acc[r][0]);
                acc[r][1] = fmaf(a4[r].y, b4[1].y, acc[r][1]);
                acc[r][2] = fmaf(a4[r].y, b4[1].z, acc[r][2]);
                acc[r][3] = fmaf(a4[r].y, b4[1].w, acc[r][3]);
                acc[r][0] = fmaf(a4[r].z, b4[2].x, acc[r][0]);
                acc[r][1] = fmaf(a4[r].z, b4[2].y, acc[r][1]);
                acc[r][2] = fmaf(a4[r].z, b4[2].z, acc[r][2]);
                acc[r][3] = fmaf(a4[r].z, b4[2].w, acc[r][3]);
                acc[r][0] = fmaf(a4[r].w, b4[3].x, acc[r][0]);
                acc[r][1] = fmaf(a4[r].w, b4[3].y, acc[r][1]);
                acc[r][2] = fmaf(a4[r].w, b4[3].z, acc[r][2]);
                acc[r][3] = fmaf(a4[r].w, b4[3].w, acc[r][3]);
            }
        }
        __syncthreads();
    }

    float4 bias = *(const float4*)&bq[tx * 4];
#pragma unroll
    for (int r = 0; r < 4; r++) {
        int gr = m0 + ty * 4 + r;
        if (gr < M) {
            float4 o;
            o.x = acc[r][0] + bias.x;
            o.y = acc[r][1] + bias.y;
            o.z = acc[r][2] + bias.z;
            o.w = acc[r][3] + bias.w;
            *(float4*)&h[gr * HID + tx * 4] = o;
        }
    }
}

// ---------------- fused edge attention + aggregate (f32x2 packed, R5) --------
__global__ __launch_bounds__(256)
void k_edge(const float* __restrict__ h, const int* __restrict__ off,
            const int* __restrict__ csr, const float* __restrict__ Wl,
            const float* __restrict__ bl, float* __restrict__ out,
            int n, int last) {
    int w = (blockIdx.x * blockDim.x + threadIdx.x) >> 5;
    if (w >= n) return;
    int lane = threadIdx.x & 31;
    const u64* hv = (const u64*)h;

    float rvx, rvy;
    upk2(rvx, rvy, hv[w * 32 + lane]);

    const float L2E = 1.4426950408889634f;
    const u64 P02 = pk2(0.2f, 0.2f);
    u64 W0p[4], cp[4];
#pragma unroll
    for (int a = 0; a < 4; a++) {
        float w0 = Wl[a] * L2E;
        float w1 = Wl[4 + a];
        float b  = bl[a];
        W0p[a] = pk2(w0, w0);
        cp[a]  = pk2(fmaf(w1, rvx, b) * L2E, fmaf(w1, rvy, b) * L2E);
    }

    int beg = off[w], end = off[w + 1];
    bool has = end > beg;

    u64 den[4], num[4];
#pragma unroll
    for (int a = 0; a < 4; a++) { den[a] = pk2(0.f, 0.f); num[a] = pk2(0.f, 0.f); }

    int i = beg;
    for (; i + 2 <= end; i += 2) {
        int sa = __ldg(&csr[i]);
        int sb = __ldg(&csr[i + 1]);
        u64 pva = hv[sa * 32 + lane];
        u64 pvb = hv[sb * 32 + lane];
#pragma unroll
        for (int a = 0; a < 4; a++) {
            u64 z2 = fma2(W0p[a], pva, cp[a]);
            u64 zs = mul2(z2, P02);
            float zl, zh, sl, sh;
            upk2(zl, zh, z2); upk2(sl, sh, zs);
            float p0 = ex2_approx(fmaxf(zl, sl));
            float p1 = ex2_approx(fmaxf(zh, sh));
            u64 pp = pk2(p0, p1);
            den[a] = add2(den[a], pp);
            num[a] = fma2(pva, pp, num[a]);
        }
#pragma unroll
        for (int a = 0; a < 4; a++) {
            u64 z2 = fma2(W0p[a], pvb, cp[a]);
            u64 zs = mul2(z2, P02);
            float zl, zh, sl, sh;
            upk2(zl, zh, z2); upk2(sl, sh, zs);
            float p0 = ex2_approx(fmaxf(zl, sl));
            float p1 = ex2_approx(fmaxf(zh, sh));
            u64 pp = pk2(p0, p1);
            den[a] = add2(den[a], pp);
            num[a] = fma2(pvb, pp, num[a]);
        }
    }
    if (i < end) {
        int sa = __ldg(&csr[i]);
        u64 pva = hv[sa * 32 + lane];
#pragma unroll
        for (int a = 0; a < 4; a++) {
            u64 z2 = fma2(W0p[a], pva, cp[a]);
            u64 zs = mul2(z2, P02);
            float zl, zh, sl, sh;
            upk2(zl, zh, z2); upk2(sl, sh, zs);
            float p0 = ex2_approx(fmaxf(zl, sl));
            float p1 = ex2_approx(fmaxf(zh, sh));
            u64 pp = pk2(p0, p1);
            den[a] = add2(den[a], pp);
            num[a] = fma2(pva, pp, num[a]);
        }
    }

    if (last) {
        float acc0 = 0.f, acc1 = 0.f;
#pragma unroll
        for (int a = 0; a < 4; a++) {
            float n0, n1, d0, d1;
            upk2(n0, n1, num[a]); upk2(d0, d1, den[a]);
            acc0 += has ? __fdividef(n0, d0) : 0.f;
            acc1 += has ? __fdividef(n1, d1) : 0.f;
        }
        float v0 = 0.25f * acc0;
        float v1 = 0.25f * acc1;
        v0 = (v0 > 0.f) ? v0 : expm1f(v0);
        v1 = (v1 > 0.f) ? v1 : expm1f(v1);
        *(float2*)&out[w * HID + 2 * lane] = make_float2(v0, v1);
    } else {
        float o[8];
#pragma unroll
        for (int a = 0; a < 4; a++) {
            float n0, n1, d0, d1;
            upk2(n0, n1, num[a]); upk2(d0, d1, den[a]);
            float g0 = has ? __fdividef(n0, d0) : 0.f;
            float g1 = has ? __fdividef(n1, d1) : 0.f;
            o[a]     = (g0 > 0.f) ? g0 : expm1f(g0);
            o[4 + a] = (g1 > 0.f) ? g1 : expm1f(g1);
        }
        *(float4*)&out[w * D1 + 8 * lane]     = make_float4(o[0], o[1], o[2], o[3]);
        *(float4*)&out[w * D1 + 8 * lane + 4] = make_float4(o[4], o[5], o[6], o[7]);
    }
}

// ---------------- launch ------------------------------------------------------
// CSR build (count/scan/scatter) depends only on senders/receivers; gemm0
// depends only on nodes/Wq0. Fork the CSR chain onto a side stream so it runs
// concurrently with gemm0; join before edge0 (standard capture fork pattern).
static cudaStream_t g_s2 = nullptr;
static cudaEvent_t  g_e0 = nullptr, g_e1 = nullptr;

extern "C" void kernel_launch(void* const* d_in, const int* in_sizes, int n_in,
                              void* d_out, int out_size) {
    const float* nodes = (const float*)d_in[0];
    const int*   send  = (const int*)d_in[1];
    const int*   recv  = (const int*)d_in[2];
    const float* Wq0 = (const float*)d_in[3];
    const float* bq0 = (const float*)d_in[4];
    const float* Wl0 = (const float*)d_in[5];
    const float* bl0 = (const float*)d_in[6];
    const float* Wq1 = (const float*)d_in[7];
    const float* bq1 = (const float*)d_in[8];
    const float* Wl1 = (const float*)d_in[9];
    const float* bl1 = (const float*)d_in[10];
    const float* Wq2 = (const float*)d_in[11];
    const float* bq2 = (const float*)d_in[12];
    const float* Wl2 = (const float*)d_in[13];
    const float* bl2 = (const float*)d_in[14];
    float* out = (float*)d_out;

    if (!g_s2) {
        cudaStreamCreateWithFlags(&g_s2, cudaStreamNonBlocking);
        cudaEventCreateWithFlags(&g_e0, cudaEventDisableTiming);
        cudaEventCreateWithFlags(&g_e1, cudaEventDisableTiming);
    }

    float *h, *x;
    int *deg, *off, *cur, *csr;
    cudaGetSymbolAddress((void**)&h,   g_h);
    cudaGetSymbolAddress((void**)&x,   g_x);
    cudaGetSymbolAddress((void**)&deg, g_deg);
    cudaGetSymbolAddress((void**)&off, g_off);
    cudaGetSymbolAddress((void**)&cur, g_cur);
    cudaGetSymbolAddress((void**)&csr, g_csr);

    int gemm_blocks = (N_NODES + 63) / 64;
    int edge_blocks = (N_NODES * 32 + 255) / 256;

    // fork: CSR chain on side stream, gemm0 on the main (capture) stream
    cudaEventRecord(g_e0, 0);
    cudaStreamWaitEvent(g_s2, g_e0, 0);
    k_count<<<(N_EDGES + 255) / 256, 256, 0, g_s2>>>(recv, deg, N_EDGES);
    k_scan<<<1, 1024, 0, g_s2>>>(deg, off, cur, N_NODES);
    k_scatter<<<(N_EDGES + 255) / 256, 256, 0, g_s2>>>(recv, send, cur, csr, deg, N_EDGES);
    cudaEventRecord(g_e1, g_s2);

    k_gemm<<<gemm_blocks, 256>>>(nodes, Wq0, bq0, h, N_NODES, 128);

    // join: edge0 needs both csr (side stream) and h (main stream)
    cudaStreamWaitEvent(0, g_e1, 0);
    k_edge<<<edge_blocks, 256>>>(h, off, csr, Wl0, bl0, x, N_NODES, 0);
    k_gemm<<<gemm_blocks, 256>>>(x, Wq1, bq1, h, N_NODES, D1);
    k_edge<<<edge_blocks, 256>>>(h, off, csr, Wl1, bl1, x, N_NODES, 0);
    k_gemm<<<gemm_blocks, 256>>>(x, Wq2, bq2, h, N_NODES, D1);
    k_edge<<<edge_blocks, 256>>>(h, off, csr, Wl2, bl2, out, N_NODES, 1);
}